// round 12
// baseline (speedup 1.0000x reference)
#include <cuda_runtime.h>
#include <cuda_bf16.h>
#include <stdint.h>

// ---------------- configuration ----------------
#define THREADS   256
#define TILE      1024                 // rows per block
#define PAIRS     2                    // row-pairs per thread (2*2*256 = 1024)
#define NCHUNK    (PAIRS * 8)          // 16 ballot-chunks
#define MAXB      16384
#define NGRP      (MAXB / 32)
#define TH        0.35f

#define FLAG64    (1ull << 62)
#define VAL48     0x0000FFFFFFFFFFFFull

// ---------------- device scratch (reset each call by reset_kernel) ----------------
__device__ unsigned long long g_blk[MAXB];     // per-block aggregate, flag bit 62
__device__ unsigned long long g_grp[NGRP];     // per-group accumulated sum, flag bit 62
__device__ unsigned           g_gcnt[NGRP];    // per-group arrival counter

// block-cooperative zero of float range [s, e) relative to base
__device__ __forceinline__ void zero_range(float* __restrict__ base,
                                           unsigned s, unsigned e, int t) {
    const float4 z4 = make_float4(0.f, 0.f, 0.f, 0.f);
    unsigned q0 = s & ~3u;
    for (unsigned qf = q0 + (unsigned)t * 4u; qf < e; qf += THREADS * 4u) {
        unsigned lo = qf > s ? qf : s;
        unsigned hi = (qf + 4u < e) ? qf + 4u : e;
        if (lo == qf && hi == qf + 4u) {
            *reinterpret_cast<float4*>(base + qf) = z4;
        } else {
            for (unsigned x = lo; x < hi; x++) base[x] = 0.0f;
        }
    }
}

// ---------------- K1: fused count + 2-level lookback + scatter + slack-zero ----------------
__global__ void __launch_bounds__(THREADS)
fused_kernel(const float4* __restrict__ q, float* __restrict__ out,
             int R, unsigned roisN, int B) {
    __shared__ unsigned mlo[PAIRS][8], mhi[PAIRS][8];
    __shared__ unsigned mloF[PAIRS][8], mhiF[PAIRS][8];
    __shared__ unsigned co[NCHUNK], coF[NCHUNK];
    __shared__ unsigned sAgg[2];

    int b = blockIdx.x, t = threadIdx.x;
    int lane = t & 31, warp = t >> 5;
    unsigned lt = (1u << lane) - 1u;
    int pairBase = b * (TILE / 2);

    // -------- phase 1: load pairs into registers, ballot --------
    float4 v0[PAIRS], v1[PAIRS], v2[PAIRS];
#pragma unroll
    for (int k = 0; k < PAIRS; k++) {
        int p = pairBase + k * THREADS + t;
        int r0 = 2 * p;
        float4 a = make_float4(1.f, 0.f, 0.f, 0.f);
        float4 c = make_float4(0.f, -1.f, 1.f, 0.f);
        float4 d = make_float4(0.f, 0.f, 0.f, -1.f);
        if (r0 < R) {
            const float4* g = q + (size_t)p * 3;
            a = __ldg(g + 0); c = __ldg(g + 1); d = __ldg(g + 2);
        }
        v0[k] = a; v1[k] = c; v2[k] = d;
        bool f0 = (r0 < R)     && (c.y >= TH);
        bool f1 = (r0 + 1 < R) && (d.w >= TH);
        bool p0 = f0 && (a.x == 0.0f);
        bool p1 = f1 && (c.z == 0.0f);
        unsigned blo  = __ballot_sync(0xffffffffu, p0);
        unsigned bhi  = __ballot_sync(0xffffffffu, p1);
        unsigned bFlo = __ballot_sync(0xffffffffu, f0);
        unsigned bFhi = __ballot_sync(0xffffffffu, f1);
        if (lane == 0) {
            mlo[k][warp] = blo;   mhi[k][warp] = bhi;
            mloF[k][warp] = bFlo; mhiF[k][warp] = bFhi;
        }
    }
    __syncthreads();

    // -------- phase 2: warp 0 — post aggregate + 2-level lookback --------
    if (warp == 0) {
        int k = (lane >> 3) & 1, w = lane & 7;
        unsigned cntT = 0, cntF = 0;
        if (lane < NCHUNK) {
            cntT = __popc(mlo[k][w])  + __popc(mhi[k][w]);
            cntF = __popc(mloF[k][w]) + __popc(mhiF[k][w]);
        }
        unsigned long long packed = (unsigned long long)cntT
                                  | ((unsigned long long)cntF << 24);
        unsigned aggT = __reduce_add_sync(0xffffffffu, cntT);
        unsigned aggF = __reduce_add_sync(0xffffffffu, cntF);
        unsigned long long aggP = (unsigned long long)aggT
                                | ((unsigned long long)aggF << 24);

        int g = b >> 5, r = b & 31;
        int members = (B - g * 32 < 32) ? (B - g * 32) : 32;
        if (lane == 0) {
            atomicExch(&g_blk[b], FLAG64 | aggP);
            // accumulate into group sum; force completion before counter bump
            unsigned long long old = atomicAdd(&g_grp[g], aggP);
            unsigned dep = (unsigned)(old >> 63);          // always 0, data dep
            unsigned c = atomicAdd(&g_gcnt[g], 1u + dep);
            if (c == (unsigned)members - 1u)
                atomicOr(&g_grp[g], FLAG64);               // publish group sum
        }

        // local inclusive scan over the 16 chunks
        unsigned long long s = packed;
#pragma unroll
        for (int o = 1; o < 32; o <<= 1) {
            unsigned long long n = __shfl_up_sync(0xffffffffu, s, o);
            if (lane >= o) s += n;
        }

        // exclusive prefix: same-group predecessors + all prior groups
        unsigned exclT = 0, exclF = 0;
        {
            unsigned long long vi = 0;
            if (lane < r) {
                do { vi = *(volatile unsigned long long*)&g_blk[g * 32 + lane]; }
                while (!(vi >> 62));
                vi &= VAL48;
            }
            exclT += __reduce_add_sync(0xffffffffu, (unsigned)(vi & 0xFFFFFFull));
            exclF += __reduce_add_sync(0xffffffffu, (unsigned)((vi >> 24) & 0xFFFFFFull));
            for (int base = g - 1; base >= 0; base -= 32) {
                int idx = base - lane;
                unsigned long long v = 0;
                if (idx >= 0) {
                    do { v = *(volatile unsigned long long*)&g_grp[idx]; }
                    while (!(v >> 62));
                    v &= VAL48;
                }
                exclT += __reduce_add_sync(0xffffffffu, (unsigned)(v & 0xFFFFFFull));
                exclF += __reduce_add_sync(0xffffffffu, (unsigned)((v >> 24) & 0xFFFFFFull));
            }
        }

        if (lane < NCHUNK) {
            unsigned sT = (unsigned)(s & 0xFFFFFFull);
            unsigned sF = (unsigned)((s >> 24) & 0xFFFFFFull);
            co [lane] = exclT + sT - cntT;
            coF[lane] = exclF + sF - cntF;
        }
        if (lane == 0) { sAgg[0] = aggT; sAgg[1] = aggF; }
        if (b == B - 1 && lane == 0) {
            out[11u * (size_t)(roisN / 5u) + 0] = (float)(exclT + aggT);
            out[11u * (size_t)(roisN / 5u) + 1] = (float)(exclF + aggF);
        }
    }
    __syncthreads();

    // -------- phase 3: stable scatter from registers --------
    float2* __restrict__ outFull2 = reinterpret_cast<float2*>(out + roisN);
#pragma unroll
    for (int k = 0; k < PAIRS; k++) {
        unsigned blo  = mlo[k][warp],  bhi  = mhi[k][warp];
        unsigned bFlo = mloF[k][warp], bFhi = mhiF[k][warp];
        unsigned baseT = co[k * 8 + warp], baseF = coF[k * 8 + warp];
        unsigned preT = __popc(blo & lt) + __popc(bhi & lt);
        unsigned preF = __popc(bFlo & lt) + __popc(bFhi & lt);
        float4 a = v0[k], c = v1[k], d = v2[k];
        // row 0 of pair
        if ((bFlo >> lane) & 1u) {
            float2* oF = outFull2 + (size_t)(baseF + preF) * 3;
            oF[0] = make_float2(a.x, a.y);
            oF[1] = make_float2(a.z, a.w);
            oF[2] = make_float2(c.x, c.y);
            if ((blo >> lane) & 1u) {
                float* o = out + (size_t)(baseT + preT) * 5;
                o[0] = 0.0f; o[1] = a.y; o[2] = a.z; o[3] = a.w; o[4] = c.x;
            }
        }
        // row 1 of pair
        if ((bFhi >> lane) & 1u) {
            unsigned posF = baseF + preF + ((bFlo >> lane) & 1u);
            float2* oF = outFull2 + (size_t)posF * 3;
            oF[0] = make_float2(c.z, c.w);
            oF[1] = make_float2(d.x, d.y);
            oF[2] = make_float2(d.z, d.w);
            if ((bhi >> lane) & 1u) {
                unsigned pos = baseT + preT + ((blo >> lane) & 1u);
                float* o = out + (size_t)pos * 5;
                o[0] = 0.0f; o[1] = c.w; o[2] = d.x; o[3] = d.y; o[4] = d.z;
            }
        }
    }

    // -------- phase 4: zero this block's slack slices (disjoint from scatter) --------
    {
        unsigned Ru = (unsigned)R;
        unsigned tileStart = (unsigned)b * TILE;
        unsigned procEnd = tileStart + TILE < Ru ? tileStart + TILE : Ru;
        unsigned exclT = co[0],  exclF = coF[0];
        unsigned incT  = exclT + sAgg[0];
        unsigned incF  = exclF + sAgg[1];
        unsigned slackA = tileStart - exclT;
        unsigned slackB = procEnd   - incT;
        zero_range(out, (Ru - slackB) * 5u, (Ru - slackA) * 5u, t);
        unsigned fslackA = tileStart - exclF;
        unsigned fslackB = procEnd   - incF;
        zero_range(out + roisN, (Ru - fslackB) * 6u, (Ru - fslackA) * 6u, t);
    }
}

// ---------------- K2: reset scan state for next replay ----------------
__global__ void reset_kernel(int B, int G) {
    int i = blockIdx.x * blockDim.x + threadIdx.x;
    if (i < B) g_blk[i] = 0ull;
    if (i < G) { g_grp[i] = 0ull; g_gcnt[i] = 0u; }
}

// ---------------- launch ----------------
extern "C" void kernel_launch(void* const* d_in, const int* in_sizes, int n_in,
                              void* d_out, int out_size) {
    const float* det = (const float*)d_in[0];
    float* out = (float*)d_out;

    int R = in_sizes[0] / 6;                 // detections: (1, R, 6)
    int B = (R + TILE - 1) / TILE;           // 4096 for R = 4M
    int G = (B + 31) / 32;                   // 128 groups
    unsigned roisN = 5u * (unsigned)R;

    fused_kernel<<<B, THREADS>>>((const float4*)det, out, R, roisN, B);
    reset_kernel<<<(B + 255) / 256, 256>>>(B, G);
}

// round 13
// speedup vs baseline: 1.1788x; 1.1788x over previous
#include <cuda_runtime.h>
#include <cuda_bf16.h>
#include <stdint.h>

// ---------------- configuration ----------------
#define THREADS   256
#define TILE      1024                 // rows per block
#define PAIRS     2                    // row-pairs per thread (2*2*256 = 1024)
#define NCHUNK    (PAIRS * 8)          // 16 ballot-chunks
#define MAXB      16384
#define TH        0.35f

// packed status: [63:62]=flag (1=agg,2=prefix), [47:24]=cntF, [23:0]=cntT
#define FLAG_A64  (1ull << 62)
#define FLAG_P64  (2ull << 62)

// ---------------- device scratch ----------------
__device__ unsigned long long g_stat[MAXB];   // reset by reset_kernel each call

// block-cooperative zero of float range [s, e) relative to base
__device__ __forceinline__ void zero_range(float* __restrict__ base,
                                           unsigned s, unsigned e, int t) {
    const float4 z4 = make_float4(0.f, 0.f, 0.f, 0.f);
    unsigned q0 = s & ~3u;
    for (unsigned qf = q0 + (unsigned)t * 4u; qf < e; qf += THREADS * 4u) {
        unsigned lo = qf > s ? qf : s;
        unsigned hi = (qf + 4u < e) ? qf + 4u : e;
        if (lo == qf && hi == qf + 4u) {
            *reinterpret_cast<float4*>(base + qf) = z4;
        } else {
            for (unsigned x = lo; x < hi; x++) base[x] = 0.0f;
        }
    }
}

__device__ __forceinline__ unsigned long long ld_stat(int idx) {
    unsigned long long s;
    if (idx >= 0) {
        do { s = *(volatile unsigned long long*)&g_stat[idx]; }
        while ((s >> 62) == 0ull);
    } else {
        s = FLAG_P64;                  // virtual prefix 0 before block 0
    }
    return s;
}

// ---------------- K1: fully fused count + lookback + scatter + slack-zero ----------------
__global__ void __launch_bounds__(THREADS)
fused_kernel(const float4* __restrict__ q, float* __restrict__ out,
             int R, unsigned roisN, int B) {
    __shared__ unsigned mlo[PAIRS][8], mhi[PAIRS][8];
    __shared__ unsigned mloF[PAIRS][8], mhiF[PAIRS][8];
    __shared__ unsigned co[NCHUNK], coF[NCHUNK];
    __shared__ unsigned sAgg[2];

    int b = blockIdx.x, t = threadIdx.x;
    int lane = t & 31, warp = t >> 5;
    unsigned lt = (1u << lane) - 1u;
    int pairBase = b * (TILE / 2);

    // -------- phase 1: load pairs into registers, ballot --------
    float4 v0[PAIRS], v1[PAIRS], v2[PAIRS];
#pragma unroll
    for (int k = 0; k < PAIRS; k++) {
        int p = pairBase + k * THREADS + t;
        int r0 = 2 * p;
        float4 a = make_float4(1.f, 0.f, 0.f, 0.f);
        float4 c = make_float4(0.f, -1.f, 1.f, 0.f);
        float4 d = make_float4(0.f, 0.f, 0.f, -1.f);
        if (r0 < R) {
            const float4* g = q + (size_t)p * 3;
            a = __ldg(g + 0); c = __ldg(g + 1); d = __ldg(g + 2);
        }
        v0[k] = a; v1[k] = c; v2[k] = d;
        // pair = [cls0,b00,b01,b02 | b03,sc0, cls1,b10 | b11,b12,b13,sc1]
        bool f0 = (r0 < R)     && (c.y >= TH);
        bool f1 = (r0 + 1 < R) && (d.w >= TH);
        bool p0 = f0 && (a.x == 0.0f);
        bool p1 = f1 && (c.z == 0.0f);
        unsigned blo  = __ballot_sync(0xffffffffu, p0);
        unsigned bhi  = __ballot_sync(0xffffffffu, p1);
        unsigned bFlo = __ballot_sync(0xffffffffu, f0);
        unsigned bFhi = __ballot_sync(0xffffffffu, f1);
        if (lane == 0) {
            mlo[k][warp] = blo;   mhi[k][warp] = bhi;
            mloF[k][warp] = bFlo; mhiF[k][warp] = bFhi;
        }
    }
    __syncthreads();

    // -------- phase 2: warp 0 — packed scan + 64-wide lookback walk --------
    if (warp == 0) {
        int k = (lane >> 3) & 1, w = lane & 7;
        unsigned cntT = 0, cntF = 0;
        if (lane < NCHUNK) {
            cntT = __popc(mlo[k][w])  + __popc(mhi[k][w]);
            cntF = __popc(mloF[k][w]) + __popc(mhiF[k][w]);
        }
        unsigned long long packed = (unsigned long long)cntT
                                  | ((unsigned long long)cntF << 24);
        unsigned aggT = __reduce_add_sync(0xffffffffu, cntT);
        unsigned aggF = __reduce_add_sync(0xffffffffu, cntF);
        unsigned long long aggP = (unsigned long long)aggT
                                | ((unsigned long long)aggF << 24);
        if (b == 0) {
            if (lane == 0) atomicExch(&g_stat[0], FLAG_P64 | aggP);
        } else if (lane == 0) {
            atomicExch(&g_stat[b], FLAG_A64 | aggP);
        }
        unsigned long long s = packed;
#pragma unroll
        for (int o = 1; o < 32; o <<= 1) {
            unsigned long long n = __shfl_up_sync(0xffffffffu, s, o);
            if (lane >= o) s += n;
        }
        unsigned exclT = 0, exclF = 0;
        if (b > 0) {
            int idx = b - 1 - lane;            // lane 0 = closest predecessor
            for (;;) {
                // near half
                unsigned long long s0 = ld_stat(idx);
                unsigned p0m = __ballot_sync(0xffffffffu, (s0 >> 62) == 2ull);
                unsigned vT0 = (unsigned)(s0 & 0xFFFFFFull);
                unsigned vF0 = (unsigned)((s0 >> 24) & 0xFFFFFFull);
                if (p0m) {
                    int first = __ffs(p0m) - 1;
                    if (lane > first) { vT0 = 0; vF0 = 0; }
                    exclT += __reduce_add_sync(0xffffffffu, vT0);
                    exclF += __reduce_add_sync(0xffffffffu, vF0);
                    break;
                }
                exclT += __reduce_add_sync(0xffffffffu, vT0);
                exclF += __reduce_add_sync(0xffffffffu, vF0);
                // far half of the 64-wide window
                unsigned long long s1 = ld_stat(idx - 32);
                unsigned p1m = __ballot_sync(0xffffffffu, (s1 >> 62) == 2ull);
                unsigned vT1 = (unsigned)(s1 & 0xFFFFFFull);
                unsigned vF1 = (unsigned)((s1 >> 24) & 0xFFFFFFull);
                if (p1m) {
                    int first = __ffs(p1m) - 1;
                    if (lane > first) { vT1 = 0; vF1 = 0; }
                    exclT += __reduce_add_sync(0xffffffffu, vT1);
                    exclF += __reduce_add_sync(0xffffffffu, vF1);
                    break;
                }
                exclT += __reduce_add_sync(0xffffffffu, vT1);
                exclF += __reduce_add_sync(0xffffffffu, vF1);
                idx -= 64;
            }
            if (lane == 0) {
                unsigned long long inc = (unsigned long long)(exclT + aggT)
                                       | ((unsigned long long)(exclF + aggF) << 24);
                atomicExch(&g_stat[b], FLAG_P64 | inc);
            }
        }
        if (lane < NCHUNK) {
            unsigned sT = (unsigned)(s & 0xFFFFFFull);
            unsigned sF = (unsigned)((s >> 24) & 0xFFFFFFull);
            co [lane] = exclT + sT - cntT;
            coF[lane] = exclF + sF - cntF;
        }
        if (lane == 0) { sAgg[0] = aggT; sAgg[1] = aggF; }
        if (b == B - 1 && lane == 0) {
            out[11u * (size_t)(roisN / 5u) + 0] = (float)(exclT + aggT);
            out[11u * (size_t)(roisN / 5u) + 1] = (float)(exclF + aggF);
        }
    }
    __syncthreads();

    // -------- phase 3: stable scatter from registers --------
    float2* __restrict__ outFull2 = reinterpret_cast<float2*>(out + roisN);
#pragma unroll
    for (int k = 0; k < PAIRS; k++) {
        unsigned blo  = mlo[k][warp],  bhi  = mhi[k][warp];
        unsigned bFlo = mloF[k][warp], bFhi = mhiF[k][warp];
        unsigned baseT = co[k * 8 + warp], baseF = coF[k * 8 + warp];
        unsigned preT = __popc(blo & lt) + __popc(bhi & lt);
        unsigned preF = __popc(bFlo & lt) + __popc(bFhi & lt);
        float4 a = v0[k], c = v1[k], d = v2[k];
        // row 0 of pair
        if ((bFlo >> lane) & 1u) {
            float2* oF = outFull2 + (size_t)(baseF + preF) * 3;
            oF[0] = make_float2(a.x, a.y);
            oF[1] = make_float2(a.z, a.w);
            oF[2] = make_float2(c.x, c.y);
            if ((blo >> lane) & 1u) {
                float* o = out + (size_t)(baseT + preT) * 5;
                o[0] = 0.0f; o[1] = a.y; o[2] = a.z; o[3] = a.w; o[4] = c.x;
            }
        }
        // row 1 of pair
        if ((bFhi >> lane) & 1u) {
            unsigned posF = baseF + preF + ((bFlo >> lane) & 1u);
            float2* oF = outFull2 + (size_t)posF * 3;
            oF[0] = make_float2(c.z, c.w);
            oF[1] = make_float2(d.x, d.y);
            oF[2] = make_float2(d.z, d.w);
            if ((bhi >> lane) & 1u) {
                unsigned pos = baseT + preT + ((blo >> lane) & 1u);
                float* o = out + (size_t)pos * 5;
                o[0] = 0.0f; o[1] = c.w; o[2] = d.x; o[3] = d.y; o[4] = d.z;
            }
        }
    }

    // -------- phase 4: zero this block's slack slices (disjoint from scatter) --------
    {
        unsigned Ru = (unsigned)R;
        unsigned tileStart = (unsigned)b * TILE;
        unsigned procEnd = tileStart + TILE < Ru ? tileStart + TILE : Ru;
        unsigned exclT = co[0],  exclF = coF[0];
        unsigned incT  = exclT + sAgg[0];
        unsigned incF  = exclF + sAgg[1];
        unsigned slackA = tileStart - exclT;
        unsigned slackB = procEnd   - incT;
        zero_range(out, (Ru - slackB) * 5u, (Ru - slackA) * 5u, t);
        unsigned fslackA = tileStart - exclF;
        unsigned fslackB = procEnd   - incF;
        zero_range(out + roisN, (Ru - fslackB) * 6u, (Ru - fslackA) * 6u, t);
    }
}

// ---------------- K2: reset lookback statuses for the next replay ----------------
__global__ void reset_kernel(int B) {
    int i = blockIdx.x * blockDim.x + threadIdx.x;
    if (i < B) g_stat[i] = 0ull;
}

// ---------------- launch ----------------
extern "C" void kernel_launch(void* const* d_in, const int* in_sizes, int n_in,
                              void* d_out, int out_size) {
    const float* det = (const float*)d_in[0];
    float* out = (float*)d_out;

    int R = in_sizes[0] / 6;                 // detections: (1, R, 6)
    int B = (R + TILE - 1) / TILE;           // 4096 for R = 4M
    unsigned roisN = 5u * (unsigned)R;

    fused_kernel<<<B, THREADS>>>((const float4*)det, out, R, roisN, B);
    reset_kernel<<<(B + 255) / 256, 256>>>(B);
}